// round 6
// baseline (speedup 1.0000x reference)
#include <cuda_runtime.h>

#define NPTS   32768
#define GRIDSZ 16
#define CDIM   64
#define NVERT  (4 * GRIDSZ * GRIDSZ * GRIDSZ)   // 16384
#define CAP    256

__device__ int  g_cnt[NVERT];     // zero-init at module load; gather resets after use
__device__ int2 g_list[NVERT * CAP];

// fused: bin points + zero output buffer
__global__ void bin_zero_kernel(const int* __restrict__ pidx,
                                const float* __restrict__ pos,
                                float4* __restrict__ out4, int nOut4)
{
    const int p = blockIdx.x * blockDim.x + threadIdx.x;   // 0..32767

    // zero out: strided float4 stores
    const float4 z = make_float4(0.f, 0.f, 0.f, 0.f);
    for (int i = p; i < nOut4; i += NPTS) out4[i] = z;

    if (p >= NPTS) return;

    const int k  = pidx[p];
    const float px = pos[p * 3 + 0] * GRIDSZ - 0.5f;
    const float py = pos[p * 3 + 1] * GRIDSZ - 0.5f;
    const float pz = pos[p * 3 + 2] * GRIDSZ - 0.5f;
    const float fx = floorf(px), fy = floorf(py), fz = floorf(pz);

    float wx[2], wy[2], wz[2];
    wx[1] = px - fx; wx[0] = 1.0f - wx[1];
    wy[1] = py - fy; wy[0] = 1.0f - wy[1];
    wz[1] = pz - fz; wz[0] = 1.0f - wz[1];

    int ix[2], iy[2], iz[2];
    ix[0] = min(max((int)fx,     0), GRIDSZ - 1);
    ix[1] = min(max((int)fx + 1, 0), GRIDSZ - 1);
    iy[0] = min(max((int)fy,     0), GRIDSZ - 1);
    iy[1] = min(max((int)fy + 1, 0), GRIDSZ - 1);
    iz[0] = min(max((int)fz,     0), GRIDSZ - 1);
    iz[1] = min(max((int)fz + 1, 0), GRIDSZ - 1);

    #pragma unroll
    for (int cz = 0; cz < 2; ++cz)
        #pragma unroll
        for (int cy = 0; cy < 2; ++cy)
            #pragma unroll
            for (int cx = 0; cx < 2; ++cx) {
                const float w = wz[cz] * wy[cy] * wx[cx];
                const int v = ((k * GRIDSZ + iz[cz]) * GRIDSZ + iy[cy]) * GRIDSZ + ix[cx];
                int slot = atomicAdd(&g_cnt[v], 1);
                if (slot < CAP)
                    g_list[v * CAP + slot] = make_int2(p, __float_as_int(w));
            }
}

#define GTPB 128

__device__ __forceinline__ void red_add_v4(float* o, float4 v) {
    asm volatile("red.global.add.v4.f32 [%0], {%1,%2,%3,%4};"
                 :: "l"(o), "f"(v.x), "f"(v.y), "f"(v.z), "f"(v.w) : "memory");
}

__device__ __forceinline__ void fma4x4(float4& a, float4 x,
                                       float4 m0, float4 m1, float4 m2, float4 m3)
{
    a.x = fmaf(x.x, m0.x, a.x); a.y = fmaf(x.x, m0.y, a.y);
    a.z = fmaf(x.x, m0.z, a.z); a.w = fmaf(x.x, m0.w, a.w);
    a.x = fmaf(x.y, m1.x, a.x); a.y = fmaf(x.y, m1.y, a.y);
    a.z = fmaf(x.y, m1.z, a.z); a.w = fmaf(x.y, m1.w, a.w);
    a.x = fmaf(x.z, m2.x, a.x); a.y = fmaf(x.z, m2.y, a.y);
    a.z = fmaf(x.z, m2.z, a.z); a.w = fmaf(x.z, m2.w, a.w);
    a.x = fmaf(x.w, m3.x, a.x); a.y = fmaf(x.w, m3.y, a.y);
    a.z = fmaf(x.w, m3.z, a.z); a.w = fmaf(x.w, m3.w, a.w);
}

__global__ void __launch_bounds__(GTPB) gather_kernel(
    const float* __restrict__ K,     // [NVERT][64][64]
    const float* __restrict__ B,     // [NVERT][64]
    const float* __restrict__ xs,    // [N][64]
    float*       __restrict__ out)   // [N][64]
{
    __shared__ float4 sM[CDIM * 16];     // [c*16+q] = K[c][4q..4q+3]
    __shared__ float  sX[16][CDIM];
    __shared__ int    sPid[16];
    __shared__ float  sW[16];
    __shared__ int    sCnt;

    const int v = blockIdx.x;
    const int tid = threadIdx.x;

    if (tid == 0) {
        int c = g_cnt[v];
        sCnt = (c > CAP) ? CAP : c;
        g_cnt[v] = 0;                 // reset for next replay (zero-init invariant)
    }
    __syncthreads();
    const int cnt = sCnt;
    if (cnt == 0) return;

    const int q   = tid & 15;    // channel quad (4 output channels)
    const int g   = tid >> 4;    // point slot within group 0..7
    const int wid = tid >> 5;    // warp 0..3; warp covers slots {2w,2w+1,2w+8,2w+9}

    const float4* Kf4 = reinterpret_cast<const float4*>(K + (size_t)v * CDIM * CDIM);
    #pragma unroll
    for (int i = 0; i < 8; ++i) sM[tid + i * GTPB] = Kf4[tid + i * GTPB];

    const float4 bq = reinterpret_cast<const float4*>(B + (size_t)v * CDIM)[q];

    for (int base = 0; base < cnt; base += 16) {
        __syncthreads();

        if (tid < 16) {
            const int s = base + tid;
            int pid = 0; float w = 0.0f;
            if (s < cnt) {
                const int2 e = g_list[v * CAP + s];
                pid = e.x; w = __int_as_float(e.y);
            }
            sPid[tid] = pid; sW[tid] = w;
        }
        __syncthreads();

        // stage xs (guarded per-slot; stale smem for dead slots is discarded later)
        if (base + g < cnt)
            reinterpret_cast<float4*>(sX[g])[q] =
                reinterpret_cast<const float4*>(xs + (size_t)sPid[g] * CDIM)[q];
        if (base + 8 + g < cnt)
            reinterpret_cast<float4*>(sX[g + 8])[q] =
                reinterpret_cast<const float4*>(xs + (size_t)sPid[g + 8] * CDIM)[q];
        __syncthreads();

        // warp-uniform pass predicates (granularity 2 slots)
        const bool doA = (base + 2 * wid)     < cnt;   // slots {2w,2w+1}
        const bool doB = (base + 8 + 2 * wid) < cnt;   // slots {2w+8,2w+9}

        float4 a0 = make_float4(0.f, 0.f, 0.f, 0.f);
        float4 a1 = make_float4(0.f, 0.f, 0.f, 0.f);

        if (doB) {
            #pragma unroll
            for (int c4 = 0; c4 < 16; ++c4) {
                const float4 x0 = reinterpret_cast<const float4*>(sX[g])[c4];
                const float4 x1 = reinterpret_cast<const float4*>(sX[g + 8])[c4];
                const float4 m0 = sM[(4 * c4 + 0) * 16 + q];
                const float4 m1 = sM[(4 * c4 + 1) * 16 + q];
                const float4 m2 = sM[(4 * c4 + 2) * 16 + q];
                const float4 m3 = sM[(4 * c4 + 3) * 16 + q];
                fma4x4(a0, x0, m0, m1, m2, m3);
                fma4x4(a1, x1, m0, m1, m2, m3);
            }
        } else if (doA) {
            #pragma unroll
            for (int c4 = 0; c4 < 16; ++c4) {
                const float4 x0 = reinterpret_cast<const float4*>(sX[g])[c4];
                const float4 m0 = sM[(4 * c4 + 0) * 16 + q];
                const float4 m1 = sM[(4 * c4 + 1) * 16 + q];
                const float4 m2 = sM[(4 * c4 + 2) * 16 + q];
                const float4 m3 = sM[(4 * c4 + 3) * 16 + q];
                fma4x4(a0, x0, m0, m1, m2, m3);
            }
        }

        if (base + g < cnt) {
            const float w = sW[g];
            float* o = out + (size_t)sPid[g] * CDIM + 4 * q;
            red_add_v4(o, make_float4(w * (a0.x + bq.x), w * (a0.y + bq.y),
                                      w * (a0.z + bq.z), w * (a0.w + bq.w)));
        }
        if (base + 8 + g < cnt) {
            const float w = sW[g + 8];
            float* o = out + (size_t)sPid[g + 8] * CDIM + 4 * q;
            red_add_v4(o, make_float4(w * (a1.x + bq.x), w * (a1.y + bq.y),
                                      w * (a1.z + bq.z), w * (a1.w + bq.w)));
        }
    }
}

extern "C" void kernel_launch(void* const* d_in, const int* in_sizes, int n_in,
                              void* d_out, int out_size)
{
    const int*   pidx = (const int*)  d_in[0];
    const float* pos  = (const float*)d_in[1];
    const float* xs   = (const float*)d_in[2];
    const float* K    = (const float*)d_in[3];
    const float* B    = (const float*)d_in[4];
    float*       out  = (float*)d_out;

    const int nOut4 = out_size / 4;
    bin_zero_kernel<<<NPTS / 256, 256>>>(pidx, pos, (float4*)d_out, nOut4);
    gather_kernel<<<NVERT, GTPB>>>(K, B, xs, out);
}

// round 7
// speedup vs baseline: 1.6089x; 1.6089x over previous
#include <cuda_runtime.h>

#define NPTS   32768
#define GRIDSZ 16
#define CDIM   64
#define NVERT  (4 * GRIDSZ * GRIDSZ * GRIDSZ)   // 16384
#define CAP    256

__device__ int  g_cnt[NVERT];
__device__ int2 g_list[NVERT * CAP];            // (point_id, weight bits)

// zero vertex counters + zero output buffer
__global__ void zero_kernel(float4* __restrict__ out4, int nOut4) {
    int i = blockIdx.x * blockDim.x + threadIdx.x;
    if (i < NVERT) g_cnt[i] = 0;
    if (i < nOut4) out4[i] = make_float4(0.f, 0.f, 0.f, 0.f);
}

__global__ void bin_points_kernel(const int* __restrict__ pidx,
                                  const float* __restrict__ pos)
{
    int p = blockIdx.x * blockDim.x + threadIdx.x;
    if (p >= NPTS) return;

    const int k  = pidx[p];
    const float px = pos[p * 3 + 0] * GRIDSZ - 0.5f;
    const float py = pos[p * 3 + 1] * GRIDSZ - 0.5f;
    const float pz = pos[p * 3 + 2] * GRIDSZ - 0.5f;
    const float fx = floorf(px), fy = floorf(py), fz = floorf(pz);

    float wx[2], wy[2], wz[2];
    wx[1] = px - fx; wx[0] = 1.0f - wx[1];
    wy[1] = py - fy; wy[0] = 1.0f - wy[1];
    wz[1] = pz - fz; wz[0] = 1.0f - wz[1];

    int ix[2], iy[2], iz[2];
    ix[0] = min(max((int)fx,     0), GRIDSZ - 1);
    ix[1] = min(max((int)fx + 1, 0), GRIDSZ - 1);
    iy[0] = min(max((int)fy,     0), GRIDSZ - 1);
    iy[1] = min(max((int)fy + 1, 0), GRIDSZ - 1);
    iz[0] = min(max((int)fz,     0), GRIDSZ - 1);
    iz[1] = min(max((int)fz + 1, 0), GRIDSZ - 1);

    #pragma unroll
    for (int cz = 0; cz < 2; ++cz)
        #pragma unroll
        for (int cy = 0; cy < 2; ++cy)
            #pragma unroll
            for (int cx = 0; cx < 2; ++cx) {
                const float w = wz[cz] * wy[cy] * wx[cx];
                const int v = ((k * GRIDSZ + iz[cz]) * GRIDSZ + iy[cy]) * GRIDSZ + ix[cx];
                int slot = atomicAdd(&g_cnt[v], 1);
                if (slot < CAP)
                    g_list[v * CAP + slot] = make_int2(p, __float_as_int(w));
            }
}

#define GTPB 128

__device__ __forceinline__ void red_add_v4(float* o, float4 v) {
    asm volatile("red.global.add.v4.f32 [%0], {%1,%2,%3,%4};"
                 :: "l"(o), "f"(v.x), "f"(v.y), "f"(v.z), "f"(v.w) : "memory");
}

__device__ __forceinline__ void fma4x4(float4& a, float4 x,
                                       float4 m0, float4 m1, float4 m2, float4 m3)
{
    a.x = fmaf(x.x, m0.x, a.x); a.y = fmaf(x.x, m0.y, a.y);
    a.z = fmaf(x.x, m0.z, a.z); a.w = fmaf(x.x, m0.w, a.w);
    a.x = fmaf(x.y, m1.x, a.x); a.y = fmaf(x.y, m1.y, a.y);
    a.z = fmaf(x.y, m1.z, a.z); a.w = fmaf(x.y, m1.w, a.w);
    a.x = fmaf(x.z, m2.x, a.x); a.y = fmaf(x.z, m2.y, a.y);
    a.z = fmaf(x.z, m2.z, a.z); a.w = fmaf(x.z, m2.w, a.w);
    a.x = fmaf(x.w, m3.x, a.x); a.y = fmaf(x.w, m3.y, a.y);
    a.z = fmaf(x.w, m3.z, a.z); a.w = fmaf(x.w, m3.w, a.w);
}

__global__ void __launch_bounds__(GTPB) gather_kernel(
    const float* __restrict__ K,     // [NVERT][64][64]
    const float* __restrict__ B,     // [NVERT][64]
    const float* __restrict__ xs,    // [N][64]
    float*       __restrict__ out)   // [N][64]
{
    __shared__ float4 sM[CDIM * 16];     // [c*16+q] = K[c][4q..4q+3]
    __shared__ float  sX[16][CDIM];
    __shared__ int    sPid[16];
    __shared__ float  sW[16];

    const int v   = blockIdx.x;
    const int tid = threadIdx.x;
    const int q   = tid & 15;    // channel quad (4 output channels)
    const int g   = tid >> 4;    // point slot 0..7 (slots g and g+8)

    // ---- issue ALL independent loads up front (cnt, bias, chunk-0 list, matrix) ----
    int cnt = g_cnt[v];                                        // LDG (no branch on it yet)
    const float4 bq = reinterpret_cast<const float4*>(B + (size_t)v * CDIM)[q];

    int2 e0 = make_int2(0, 0);
    if (tid < 16) e0 = g_list[v * CAP + tid];  // stale/garbage pids are in-bounds; masked later

    const float4* Kf4 = reinterpret_cast<const float4*>(K + (size_t)v * CDIM * CDIM);
    float4 mv[8];
    #pragma unroll
    for (int i = 0; i < 8; ++i) mv[i] = Kf4[tid + i * GTPB];

    if (tid < 16) { sPid[tid] = e0.x; sW[tid] = __int_as_float(e0.y); }
    #pragma unroll
    for (int i = 0; i < 8; ++i) sM[tid + i * GTPB] = mv[i];

    if (cnt > CAP) cnt = CAP;

    for (int base = 0; base < cnt; base += 16) {
        if (base > 0) {   // chunk 0 list already staged
            __syncthreads();
            if (tid < 16) {
                const int2 e = g_list[v * CAP + base + tid];   // always in-bounds (<= CAP)
                sPid[tid] = e.x; sW[tid] = __int_as_float(e.y);
            }
        }
        __syncthreads();

        const bool two = (base + 8 < cnt);   // block-uniform

        {
            const int p0 = sPid[g];
            reinterpret_cast<float4*>(sX[g])[q] =
                reinterpret_cast<const float4*>(xs + (size_t)p0 * CDIM)[q];
            if (two) {
                const int p1 = sPid[g + 8];
                reinterpret_cast<float4*>(sX[g + 8])[q] =
                    reinterpret_cast<const float4*>(xs + (size_t)p1 * CDIM)[q];
            }
        }
        __syncthreads();

        float4 a0 = make_float4(0.f, 0.f, 0.f, 0.f);
        float4 a1 = make_float4(0.f, 0.f, 0.f, 0.f);

        if (two) {
            #pragma unroll
            for (int c4 = 0; c4 < 16; ++c4) {
                const float4 x0 = reinterpret_cast<const float4*>(sX[g])[c4];
                const float4 x1 = reinterpret_cast<const float4*>(sX[g + 8])[c4];
                const float4 m0 = sM[(4 * c4 + 0) * 16 + q];
                const float4 m1 = sM[(4 * c4 + 1) * 16 + q];
                const float4 m2 = sM[(4 * c4 + 2) * 16 + q];
                const float4 m3 = sM[(4 * c4 + 3) * 16 + q];
                fma4x4(a0, x0, m0, m1, m2, m3);
                fma4x4(a1, x1, m0, m1, m2, m3);
            }
        } else {
            #pragma unroll
            for (int c4 = 0; c4 < 16; ++c4) {
                const float4 x0 = reinterpret_cast<const float4*>(sX[g])[c4];
                const float4 m0 = sM[(4 * c4 + 0) * 16 + q];
                const float4 m1 = sM[(4 * c4 + 1) * 16 + q];
                const float4 m2 = sM[(4 * c4 + 2) * 16 + q];
                const float4 m3 = sM[(4 * c4 + 3) * 16 + q];
                fma4x4(a0, x0, m0, m1, m2, m3);
            }
        }

        if (base + g < cnt) {
            const float w = sW[g];
            float* o = out + (size_t)sPid[g] * CDIM + 4 * q;
            red_add_v4(o, make_float4(w * (a0.x + bq.x), w * (a0.y + bq.y),
                                      w * (a0.z + bq.z), w * (a0.w + bq.w)));
        }
        if (two && (base + 8 + g < cnt)) {
            const float w = sW[g + 8];
            float* o = out + (size_t)sPid[g + 8] * CDIM + 4 * q;
            red_add_v4(o, make_float4(w * (a1.x + bq.x), w * (a1.y + bq.y),
                                      w * (a1.z + bq.z), w * (a1.w + bq.w)));
        }
    }
}

extern "C" void kernel_launch(void* const* d_in, const int* in_sizes, int n_in,
                              void* d_out, int out_size)
{
    const int*   pidx = (const int*)  d_in[0];
    const float* pos  = (const float*)d_in[1];
    const float* xs   = (const float*)d_in[2];
    const float* K    = (const float*)d_in[3];
    const float* B    = (const float*)d_in[4];
    float*       out  = (float*)d_out;

    const int nOut4 = out_size / 4;
    const int zN    = (nOut4 > NVERT ? nOut4 : NVERT);
    zero_kernel<<<(zN + 255) / 256, 256>>>((float4*)d_out, nOut4);
    bin_points_kernel<<<(NPTS + 127) / 128, 128>>>(pidx, pos);
    gather_kernel<<<NVERT, GTPB>>>(K, B, xs, out);
}

// round 8
// speedup vs baseline: 1.6905x; 1.0507x over previous
#include <cuda_runtime.h>

#define NPTS   32768
#define GRIDSZ 16
#define CDIM   64
#define NVERT  (4 * GRIDSZ * GRIDSZ * GRIDSZ)   // 16384
#define CAP    256
#define VPB    4                                 // vertices per CTA
#define GTPB   128

__device__ int  g_cnt[NVERT];
__device__ int2 g_list[NVERT * CAP];            // (point_id, weight bits)

__global__ void zero_kernel(float4* __restrict__ out4, int nOut4) {
    int i = blockIdx.x * blockDim.x + threadIdx.x;
    if (i < NVERT) g_cnt[i] = 0;
    if (i < nOut4) out4[i] = make_float4(0.f, 0.f, 0.f, 0.f);
}

__global__ void bin_points_kernel(const int* __restrict__ pidx,
                                  const float* __restrict__ pos)
{
    int p = blockIdx.x * blockDim.x + threadIdx.x;
    if (p >= NPTS) return;

    const int k  = pidx[p];
    const float px = pos[p * 3 + 0] * GRIDSZ - 0.5f;
    const float py = pos[p * 3 + 1] * GRIDSZ - 0.5f;
    const float pz = pos[p * 3 + 2] * GRIDSZ - 0.5f;
    const float fx = floorf(px), fy = floorf(py), fz = floorf(pz);

    float wx[2], wy[2], wz[2];
    wx[1] = px - fx; wx[0] = 1.0f - wx[1];
    wy[1] = py - fy; wy[0] = 1.0f - wy[1];
    wz[1] = pz - fz; wz[0] = 1.0f - wz[1];

    int ix[2], iy[2], iz[2];
    ix[0] = min(max((int)fx,     0), GRIDSZ - 1);
    ix[1] = min(max((int)fx + 1, 0), GRIDSZ - 1);
    iy[0] = min(max((int)fy,     0), GRIDSZ - 1);
    iy[1] = min(max((int)fy + 1, 0), GRIDSZ - 1);
    iz[0] = min(max((int)fz,     0), GRIDSZ - 1);
    iz[1] = min(max((int)fz + 1, 0), GRIDSZ - 1);

    #pragma unroll
    for (int cz = 0; cz < 2; ++cz)
        #pragma unroll
        for (int cy = 0; cy < 2; ++cy)
            #pragma unroll
            for (int cx = 0; cx < 2; ++cx) {
                const float w = wz[cz] * wy[cy] * wx[cx];
                const int v = ((k * GRIDSZ + iz[cz]) * GRIDSZ + iy[cy]) * GRIDSZ + ix[cx];
                int slot = atomicAdd(&g_cnt[v], 1);
                if (slot < CAP)
                    g_list[v * CAP + slot] = make_int2(p, __float_as_int(w));
            }
}

__device__ __forceinline__ void red_add_v4(float* o, float4 v) {
    asm volatile("red.global.add.v4.f32 [%0], {%1,%2,%3,%4};"
                 :: "l"(o), "f"(v.x), "f"(v.y), "f"(v.z), "f"(v.w) : "memory");
}

__device__ __forceinline__ void cp_async16(unsigned smem_dst, const void* gptr) {
    asm volatile("cp.async.cg.shared.global [%0], [%1], 16;"
                 :: "r"(smem_dst), "l"(gptr));
}

__device__ __forceinline__ void fma4x4(float4& a, float4 x,
                                       float4 m0, float4 m1, float4 m2, float4 m3)
{
    a.x = fmaf(x.x, m0.x, a.x); a.y = fmaf(x.x, m0.y, a.y);
    a.z = fmaf(x.x, m0.z, a.z); a.w = fmaf(x.x, m0.w, a.w);
    a.x = fmaf(x.y, m1.x, a.x); a.y = fmaf(x.y, m1.y, a.y);
    a.z = fmaf(x.y, m1.z, a.z); a.w = fmaf(x.y, m1.w, a.w);
    a.x = fmaf(x.z, m2.x, a.x); a.y = fmaf(x.z, m2.y, a.y);
    a.z = fmaf(x.z, m2.z, a.z); a.w = fmaf(x.z, m2.w, a.w);
    a.x = fmaf(x.w, m3.x, a.x); a.y = fmaf(x.w, m3.y, a.y);
    a.z = fmaf(x.w, m3.z, a.z); a.w = fmaf(x.w, m3.w, a.w);
}

__global__ void __launch_bounds__(GTPB) gather_kernel(
    const float* __restrict__ K,     // [NVERT][64][64]
    const float* __restrict__ B,     // [NVERT][64]
    const float* __restrict__ xs,    // [N][64]
    float*       __restrict__ out)   // [N][64]
{
    __shared__ float4 sM[2][CDIM * 16];  // double-buffered matrix
    __shared__ float  sX[16][CDIM];
    __shared__ int    sPid[16];
    __shared__ float  sW[16];

    const int tid = threadIdx.x;
    const int v0  = blockIdx.x * VPB;
    const int q   = tid & 15;    // channel quad
    const int g   = tid >> 4;    // point slot 0..7

    // preload all counts (uniform broadcast loads)
    int cnts[VPB];
    #pragma unroll
    for (int i = 0; i < VPB; ++i) {
        int c = __ldg(&g_cnt[v0 + i]);
        cnts[i] = (c > CAP) ? CAP : c;
    }

    // prefetch matrix for vertex 0 into buf 0
    {
        const float4* Kf4 = reinterpret_cast<const float4*>(K + (size_t)v0 * CDIM * CDIM);
        unsigned dst = (unsigned)__cvta_generic_to_shared(&sM[0][0]);
        #pragma unroll
        for (int j = 0; j < 8; ++j)
            cp_async16(dst + (unsigned)(tid + j * GTPB) * 16u, Kf4 + tid + j * GTPB);
        asm volatile("cp.async.commit_group;");
    }

    #pragma unroll 1
    for (int i = 0; i < VPB; ++i) {
        const int v   = v0 + i;
        const int cnt = cnts[i];
        const int buf = i & 1;

        __syncthreads();   // all reads of sM[buf^1] (vertex i-1) complete

        // prefetch next matrix into the other buffer
        if (i + 1 < VPB) {
            const float4* Kn =
                reinterpret_cast<const float4*>(K + (size_t)(v + 1) * CDIM * CDIM);
            unsigned dst = (unsigned)__cvta_generic_to_shared(&sM[buf ^ 1][0]);
            #pragma unroll
            for (int j = 0; j < 8; ++j)
                cp_async16(dst + (unsigned)(tid + j * GTPB) * 16u, Kn + tid + j * GTPB);
        }
        asm volatile("cp.async.commit_group;");   // empty group on last iter keeps counts right

        // independent loads overlapped with matrix wait
        const float4 bq = reinterpret_cast<const float4*>(B + (size_t)v * CDIM)[q];
        int2 e = make_int2(0, 0);
        if (tid < 16 && cnt > 0) e = g_list[v * CAP + tid];

        asm volatile("cp.async.wait_group 1;");   // matrix for vertex i landed
        __syncthreads();                          // visible to all warps

        const float4* sMb = sM[buf];

        for (int base = 0; base < cnt; base += 16) {
            if (tid < 16) { sPid[tid] = e.x; sW[tid] = __int_as_float(e.y); }
            __syncthreads();

            const bool two = (base + 8 < cnt);   // block-uniform
            const int  pid0 = sPid[g], pid1 = sPid[g + 8];
            const float w0 = sW[g],    w1  = sW[g + 8];

            reinterpret_cast<float4*>(sX[g])[q] =
                reinterpret_cast<const float4*>(xs + (size_t)pid0 * CDIM)[q];
            if (two)
                reinterpret_cast<float4*>(sX[g + 8])[q] =
                    reinterpret_cast<const float4*>(xs + (size_t)pid1 * CDIM)[q];
            __syncthreads();

            // prefetch next chunk's list entry during compute
            if (tid < 16 && base + 16 < cnt) e = g_list[v * CAP + base + 16 + tid];

            float4 a0 = make_float4(0.f, 0.f, 0.f, 0.f);
            float4 a1 = make_float4(0.f, 0.f, 0.f, 0.f);

            if (two) {
                #pragma unroll
                for (int c4 = 0; c4 < 16; ++c4) {
                    const float4 x0 = reinterpret_cast<const float4*>(sX[g])[c4];
                    const float4 x1 = reinterpret_cast<const float4*>(sX[g + 8])[c4];
                    const float4 m0 = sMb[(4 * c4 + 0) * 16 + q];
                    const float4 m1 = sMb[(4 * c4 + 1) * 16 + q];
                    const float4 m2 = sMb[(4 * c4 + 2) * 16 + q];
                    const float4 m3 = sMb[(4 * c4 + 3) * 16 + q];
                    fma4x4(a0, x0, m0, m1, m2, m3);
                    fma4x4(a1, x1, m0, m1, m2, m3);
                }
            } else {
                #pragma unroll
                for (int c4 = 0; c4 < 16; ++c4) {
                    const float4 x0 = reinterpret_cast<const float4*>(sX[g])[c4];
                    const float4 m0 = sMb[(4 * c4 + 0) * 16 + q];
                    const float4 m1 = sMb[(4 * c4 + 1) * 16 + q];
                    const float4 m2 = sMb[(4 * c4 + 2) * 16 + q];
                    const float4 m3 = sMb[(4 * c4 + 3) * 16 + q];
                    fma4x4(a0, x0, m0, m1, m2, m3);
                }
            }

            if (base + g < cnt) {
                float* o = out + (size_t)pid0 * CDIM + 4 * q;
                red_add_v4(o, make_float4(w0 * (a0.x + bq.x), w0 * (a0.y + bq.y),
                                          w0 * (a0.z + bq.z), w0 * (a0.w + bq.w)));
            }
            if (two && (base + 8 + g < cnt)) {
                float* o = out + (size_t)pid1 * CDIM + 4 * q;
                red_add_v4(o, make_float4(w1 * (a1.x + bq.x), w1 * (a1.y + bq.y),
                                          w1 * (a1.z + bq.z), w1 * (a1.w + bq.w)));
            }
        }
    }
}

extern "C" void kernel_launch(void* const* d_in, const int* in_sizes, int n_in,
                              void* d_out, int out_size)
{
    const int*   pidx = (const int*)  d_in[0];
    const float* pos  = (const float*)d_in[1];
    const float* xs   = (const float*)d_in[2];
    const float* K    = (const float*)d_in[3];
    const float* B    = (const float*)d_in[4];
    float*       out  = (float*)d_out;

    const int nOut4 = out_size / 4;
    const int zN    = (nOut4 > NVERT ? nOut4 : NVERT);
    zero_kernel<<<(zN + 255) / 256, 256>>>((float4*)d_out, nOut4);
    bin_points_kernel<<<(NPTS + 127) / 128, 128>>>(pidx, pos);
    gather_kernel<<<NVERT / VPB, GTPB>>>(K, B, xs, out);
}